// round 6
// baseline (speedup 1.0000x reference)
#include <cuda_runtime.h>
#include <cstdint>

// MessagePassing: out[src[e], k] += edge_attrs_flat[k*E + e]
// edge_attrs: float32 [E*F] (values consumed as (F,E): contiguous in e per feature)
// attr_idx:   [2*E] ints (row 0 = src); int32 or int64, detected per-block
// out:        float32 [N*F]
//
// Bottleneck (measured R2 vs R4 invariance): L2 atomic RMW throughput,
// ~2.2 cyc per RED.128 per LTS slice. Loads are not the constraint.

static constexpr int F = 16;
static constexpr int TPB = 256;
static constexpr int EDGES_PER_THREAD = 4;
static constexpr int EDGES_PER_BLOCK = TPB * EDGES_PER_THREAD;  // 1024

__global__ void zero_out_kernel(float4* __restrict__ out4, int n4) {
    int i = blockIdx.x * blockDim.x + threadIdx.x;
    if (i < n4) out4[i] = make_float4(0.f, 0.f, 0.f, 0.f);
}

// 4 edges per thread, float4 streaming loads along e; per-block idx-dtype sniff.
__global__ void __launch_bounds__(TPB)
scatter4_kernel(const float* __restrict__ attrs,
                const void* __restrict__ src_idx,
                float* __restrict__ out,
                int E, int n_groups) {
    __shared__ int s_not64;

    int tid = threadIdx.x;
    if (tid == 0) s_not64 = 0;
    __syncthreads();

    // Per-block dtype sniff on this block's own edge range.
    // If int64 (LE), the int32 word at position 2e+1 is a high word -> 0.
    // If int32, it's a random index in [0,100000): nonzero w.p. 1-1e-5.
    // 64 samples all zero => int64 (p_false ~ 1e-320). Position 2e+1 with
    // e < E is in-bounds under both interpretations (buffer >= 2E int32 words).
    long long block_first_edge = (long long)blockIdx.x * EDGES_PER_BLOCK;
    if (tid < 64) {
        long long e = block_first_edge + (long long)tid * 16;
        if (e >= E) e = (long long)tid % E;   // last partial block: sample anywhere valid
        int hi = __ldcs((const int*)src_idx + (2 * e + 1));
        if (hi != 0) atomicOr(&s_not64, 1);
    }
    __syncthreads();
    bool is64 = !s_not64;

    int t = blockIdx.x * TPB + tid;
    if (t >= n_groups) return;

    int src[4];
    if (is64) {
        const longlong2* p = (const longlong2*)src_idx + 2 * t;
        longlong2 a = __ldcs(p);
        longlong2 b = __ldcs(p + 1);
        src[0] = (int)a.x; src[1] = (int)a.y;
        src[2] = (int)b.x; src[3] = (int)b.y;
    } else {
        int4 a = __ldcs((const int4*)src_idx + t);
        src[0] = a.x; src[1] = a.y; src[2] = a.z; src[3] = a.w;
    }

    // v[k] = float4 of feature k for edges 4t..4t+3 (streaming: single-use)
    float4 v[F];
#pragma unroll
    for (int k = 0; k < F; k++) {
        v[k] = __ldcs((const float4*)(attrs + (size_t)k * (size_t)E + (size_t)(4 * t)));
    }

    // Edge j uses component j of every v[k].
#pragma unroll
    for (int j = 0; j < 4; j++) {
        const float* vj = ((const float*)&v[0]) + j;  // stride 4 floats between ks
        float* dst = out + (size_t)src[j] * F;
#pragma unroll
        for (int kg = 0; kg < F; kg += 4) {
            asm volatile(
                "red.global.add.v4.f32 [%0], {%1, %2, %3, %4};"
                :: "l"(dst + kg),
                   "f"(vj[4 * (kg + 0)]), "f"(vj[4 * (kg + 1)]),
                   "f"(vj[4 * (kg + 2)]), "f"(vj[4 * (kg + 3)])
                : "memory");
        }
    }
}

// Scalar tail for E % 4 != 0 (not hit for E=4M; self-detects dtype too).
__global__ void scatter_tail_kernel(const float* __restrict__ attrs,
                                    const void* __restrict__ src_idx,
                                    float* __restrict__ out,
                                    int E, int e_begin) {
    __shared__ int s_not64;
    if (threadIdx.x == 0) s_not64 = 0;
    __syncthreads();
    if (threadIdx.x < 64) {
        long long e = (long long)threadIdx.x % E;
        if (__ldcs((const int*)src_idx + (2 * e + 1)) != 0) atomicOr(&s_not64, 1);
    }
    __syncthreads();
    bool is64 = !s_not64;

    int e = e_begin + blockIdx.x * blockDim.x + threadIdx.x;
    if (e >= E) return;
    int src = is64 ? (int)((const long long*)src_idx)[e]
                   : ((const int*)src_idx)[e];
    float v[F];
#pragma unroll
    for (int k = 0; k < F; k++) v[k] = attrs[(size_t)k * (size_t)E + e];
    float* dst = out + (size_t)src * F;
#pragma unroll
    for (int kg = 0; kg < F; kg += 4) {
        asm volatile(
            "red.global.add.v4.f32 [%0], {%1, %2, %3, %4};"
            :: "l"(dst + kg), "f"(v[kg]), "f"(v[kg + 1]), "f"(v[kg + 2]), "f"(v[kg + 3])
            : "memory");
    }
}

extern "C" void kernel_launch(void* const* d_in, const int* in_sizes, int n_in,
                              void* d_out, int out_size) {
    const float* attrs = (const float*)d_in[0];
    const void* attr_idx = d_in[1];        // (2, E), row 0 = src
    float* out = (float*)d_out;

    int E = in_sizes[0] / F;

    int n4 = out_size / 4;
    zero_out_kernel<<<(n4 + 255) / 256, 256>>>((float4*)out, n4);

    int n_groups = E / 4;
    if (n_groups > 0) {
        int blocks = (n_groups + TPB - 1) / TPB;
        scatter4_kernel<<<blocks, TPB>>>(attrs, attr_idx, out, E, n_groups);
    }

    int rem_begin = n_groups * 4;
    int rem = E - rem_begin;
    if (rem > 0)
        scatter_tail_kernel<<<(rem + 255) / 256, 256>>>(attrs, attr_idx, out, E, rem_begin);
}

// round 7
// speedup vs baseline: 1.2497x; 1.2497x over previous
#include <cuda_runtime.h>
#include <cstdint>

// MessagePassing: out[src[e], k] += edge_attrs_flat[k*E + e]
// edge_attrs: float32 [E*F] (values consumed as (F,E): contiguous in e per feature)
// attr_idx:   [2*E] ints (row 0 = src); int32 or int64, detected per-block
// out:        float32 [N*F]
//
// Layout: 4 consecutive lanes own one edge (lane r handles features 4r..4r+3),
// so each RED.128 warp-instruction touches only ~8 distinct 64B node rows
// (4 lanes contiguous per row) instead of 32 scattered lines.

static constexpr int F = 16;
static constexpr int TPB = 256;
static constexpr int ITER = 4;   // edges per edge-slot

__global__ void zero_out_kernel(float4* __restrict__ out4, int n4) {
    int i = blockIdx.x * blockDim.x + threadIdx.x;
    if (i < n4) out4[i] = make_float4(0.f, 0.f, 0.f, 0.f);
}

__global__ void __launch_bounds__(TPB)
scatter_fs_kernel(const float* __restrict__ attrs,
                  const void* __restrict__ src_idx,
                  float* __restrict__ out,
                  int E, int n_slots) {
    __shared__ int s_not64;
    int tid = threadIdx.x;
    if (tid == 0) s_not64 = 0;
    __syncthreads();

    // Per-block idx dtype sniff: under little-endian int64, int32 word at
    // position 2e+1 is a high word -> 0. Random int32 indices in [0,100000)
    // are nonzero w.p. 1-1e-5; 64 all-zero samples => int64.
    if (tid < 64) {
        long long e = ((long long)blockIdx.x * 64 + tid) % E;
        if (__ldcs((const int*)src_idx + (2 * e + 1)) != 0) atomicOr(&s_not64, 1);
    }
    __syncthreads();
    bool is64 = !s_not64;

    int gtid = blockIdx.x * TPB + tid;
    int slot = gtid >> 2;          // edge slot: shared by 4 consecutive lanes
    int kg = (gtid & 3) * 4;       // this lane's feature quarter

    if (slot >= n_slots) return;

    const float* arow0 = attrs + (size_t)(kg + 0) * (size_t)E;
    const float* arow1 = attrs + (size_t)(kg + 1) * (size_t)E;
    const float* arow2 = attrs + (size_t)(kg + 2) * (size_t)E;
    const float* arow3 = attrs + (size_t)(kg + 3) * (size_t)E;

#pragma unroll
    for (int it = 0; it < ITER; it++) {
        long long e = (long long)it * n_slots + slot;   // coalesced across warp
        if (e >= E) break;

        int src = is64 ? (int)__ldcs((const long long*)src_idx + e)
                       : __ldcs((const int*)src_idx + e);

        float v0 = __ldcs(arow0 + e);
        float v1 = __ldcs(arow1 + e);
        float v2 = __ldcs(arow2 + e);
        float v3 = __ldcs(arow3 + e);

        float* dst = out + (size_t)src * F + kg;
        asm volatile(
            "red.global.add.v4.f32 [%0], {%1, %2, %3, %4};"
            :: "l"(dst), "f"(v0), "f"(v1), "f"(v2), "f"(v3)
            : "memory");
    }
}

extern "C" void kernel_launch(void* const* d_in, const int* in_sizes, int n_in,
                              void* d_out, int out_size) {
    const float* attrs = (const float*)d_in[0];
    const void* attr_idx = d_in[1];        // (2, E), row 0 = src
    float* out = (float*)d_out;

    int E = in_sizes[0] / F;

    int n4 = out_size / 4;
    zero_out_kernel<<<(n4 + 255) / 256, 256>>>((float4*)out, n4);

    int n_slots = (E + ITER - 1) / ITER;
    long long n_threads = (long long)n_slots * 4;
    int blocks = (int)((n_threads + TPB - 1) / TPB);
    scatter_fs_kernel<<<blocks, TPB>>>(attrs, attr_idx, out, E, n_slots);
}

// round 8
// speedup vs baseline: 1.4971x; 1.1980x over previous
#include <cuda_runtime.h>
#include <cstdint>

// MessagePassing: out[src[e], k] += edge_attrs_flat[k*E + e]
// edge_attrs: float32 [E*F] (values consumed as (F,E): contiguous in e per feature)
// attr_idx:   [2*E] ints (row 0 = src); int32 or int64, detected per-block
// out:        float32 [N*F]
//
// Layout: a 4-lane group owns 4 consecutive edges. Lane kgq owns feature
// quarter kg=4*kgq. It loads float4 (4 edges) from each of its 4 feature rows
// (dense 128B lines per warp instruction), register-transposes, and issues one
// RED.v4 per edge. Within each RED warp-instruction the 4 lanes of a group
// write the contiguous 64B row of ONE node -> 8 node lines per instruction.

static constexpr int F = 16;
static constexpr int TPB = 256;

__global__ void zero_out_kernel(float4* __restrict__ out4, int n4) {
    int i = blockIdx.x * blockDim.x + threadIdx.x;
    if (i < n4) out4[i] = make_float4(0.f, 0.f, 0.f, 0.f);
}

__global__ void __launch_bounds__(TPB)
scatter_rt_kernel(const float* __restrict__ attrs,
                  const void* __restrict__ src_idx,
                  float* __restrict__ out,
                  int E, int n_groups) {
    __shared__ int s_not64;
    int tid = threadIdx.x;
    if (tid == 0) s_not64 = 0;
    __syncthreads();

    // Per-block idx dtype sniff: under little-endian int64, int32 word at
    // position 2e+1 is a high word -> 0. Random int32 indices in [0,100000)
    // are nonzero w.p. 1-1e-5; 64 all-zero samples => int64.
    if (tid < 64) {
        long long e = ((long long)blockIdx.x * 64 + tid) % E;
        if (__ldcs((const int*)src_idx + (2 * e + 1)) != 0) atomicOr(&s_not64, 1);
    }
    __syncthreads();
    bool is64 = !s_not64;

    int gtid = blockIdx.x * TPB + tid;
    int group = gtid >> 2;          // 4-edge group, shared by 4 consecutive lanes
    int kg = (gtid & 3) * 4;        // this lane's feature quarter

    if (group >= n_groups) return;

    size_t e0 = (size_t)group * 4;  // first of this group's 4 edges (full groups only)

    // Indices of the 4 edges (16B broadcast within the group).
    int src[4];
    if (is64) {
        const longlong2* p = (const longlong2*)src_idx + 2 * group;
        longlong2 a = __ldcs(p);
        longlong2 b = __ldcs(p + 1);
        src[0] = (int)a.x; src[1] = (int)a.y;
        src[2] = (int)b.x; src[3] = (int)b.y;
    } else {
        int4 a = __ldcs((const int4*)src_idx + group);
        src[0] = a.x; src[1] = a.y; src[2] = a.z; src[3] = a.w;
    }

    // Dense float4 loads: row kg+i, edges e0..e0+3. Per warp instruction:
    // 4 rows x 128B dense = 4 lines for 512B.
    float4 v0 = __ldcs((const float4*)(attrs + (size_t)(kg + 0) * (size_t)E + e0));
    float4 v1 = __ldcs((const float4*)(attrs + (size_t)(kg + 1) * (size_t)E + e0));
    float4 v2 = __ldcs((const float4*)(attrs + (size_t)(kg + 2) * (size_t)E + e0));
    float4 v3 = __ldcs((const float4*)(attrs + (size_t)(kg + 3) * (size_t)E + e0));

    const float* c0 = (const float*)&v0;
    const float* c1 = (const float*)&v1;
    const float* c2 = (const float*)&v2;
    const float* c3 = (const float*)&v3;

    // One RED.v4 per edge j; 4 lanes of the group cover the node's 64B row.
#pragma unroll
    for (int j = 0; j < 4; j++) {
        float* dst = out + (size_t)src[j] * F + kg;
        asm volatile(
            "red.global.add.v4.f32 [%0], {%1, %2, %3, %4};"
            :: "l"(dst), "f"(c0[j]), "f"(c1[j]), "f"(c2[j]), "f"(c3[j])
            : "memory");
    }
}

// Scalar tail for E % 4 != 0 (not hit for E=4M; self-detects dtype).
__global__ void scatter_tail_kernel(const float* __restrict__ attrs,
                                    const void* __restrict__ src_idx,
                                    float* __restrict__ out,
                                    int E, int e_begin) {
    __shared__ int s_not64;
    if (threadIdx.x == 0) s_not64 = 0;
    __syncthreads();
    if (threadIdx.x < 64) {
        long long e = (long long)threadIdx.x % E;
        if (__ldcs((const int*)src_idx + (2 * e + 1)) != 0) atomicOr(&s_not64, 1);
    }
    __syncthreads();
    bool is64 = !s_not64;

    int e = e_begin + blockIdx.x * blockDim.x + threadIdx.x;
    if (e >= E) return;
    int src = is64 ? (int)((const long long*)src_idx)[e]
                   : ((const int*)src_idx)[e];
    float v[F];
#pragma unroll
    for (int k = 0; k < F; k++) v[k] = attrs[(size_t)k * (size_t)E + e];
    float* dst = out + (size_t)src * F;
#pragma unroll
    for (int kg = 0; kg < F; kg += 4) {
        asm volatile(
            "red.global.add.v4.f32 [%0], {%1, %2, %3, %4};"
            :: "l"(dst + kg), "f"(v[kg]), "f"(v[kg + 1]), "f"(v[kg + 2]), "f"(v[kg + 3])
            : "memory");
    }
}

extern "C" void kernel_launch(void* const* d_in, const int* in_sizes, int n_in,
                              void* d_out, int out_size) {
    const float* attrs = (const float*)d_in[0];
    const void* attr_idx = d_in[1];        // (2, E), row 0 = src
    float* out = (float*)d_out;

    int E = in_sizes[0] / F;

    int n4 = out_size / 4;
    zero_out_kernel<<<(n4 + 255) / 256, 256>>>((float4*)out, n4);

    int n_groups = E / 4;                  // full 4-edge groups
    if (n_groups > 0) {
        long long n_threads = (long long)n_groups * 4;
        int blocks = (int)((n_threads + TPB - 1) / TPB);
        scatter_rt_kernel<<<blocks, TPB>>>(attrs, attr_idx, out, E, n_groups);
    }

    int rem_begin = n_groups * 4;
    int rem = E - rem_begin;
    if (rem > 0)
        scatter_tail_kernel<<<(rem + 255) / 256, 256>>>(attrs, attr_idx, out, E, rem_begin);
}

// round 12
// speedup vs baseline: 1.6415x; 1.0964x over previous
#include <cuda_runtime.h>
#include <cstdint>

// MessagePassing: out[src[e], k] += edge_attrs_flat[k*E + e]
// edge_attrs: float32 [E*F] (values consumed as (F,E): contiguous in e per feature)
// attr_idx:   [2*E] ints (row 0 = src); int32 or int64, sniffed once in zero kernel
// out:        float32 [N*F]
//
// Layout: a 4-lane group owns 4 consecutive edges. Lane kgq owns feature
// quarter kg=4*kgq; it loads float4 (4 edges) from its 4 feature rows (dense
// 128B lines per warp instruction), register-transposes, and issues one
// RED.v4 per edge (4 lanes cover one node's 64B row -> 8 node lines/instr).
// Each thread processes TWO group chunks (t and t+G2) with all 10 loads
// front-batched for MLP; REDs are fire-and-forget.

static constexpr int F = 16;
static constexpr int TPB = 256;

__device__ int g_idx_is64;

__global__ void zero_out_kernel(float4* __restrict__ out4, int n4,
                                const int* __restrict__ idx32, long long E) {
    // Block 0, lanes 0-63: idx dtype sniff. Under little-endian int64 the
    // int32 word at position 2e+1 is a high word -> 0. Random int32 indices
    // in [0,100000) are nonzero w.p. 1-1e-5; 64 all-zero samples => int64.
    if (blockIdx.x == 0) {
        __shared__ int s_not64;
        if (threadIdx.x == 0) s_not64 = 0;
        __syncthreads();
        if (threadIdx.x < 64) {
            long long e = ((long long)threadIdx.x * (E / 64)) % E;
            if (__ldcs(idx32 + (2 * e + 1)) != 0) atomicOr(&s_not64, 1);
        }
        __syncthreads();
        if (threadIdx.x == 0) g_idx_is64 = !s_not64;
    }
    int i = blockIdx.x * blockDim.x + threadIdx.x;
    if (i < n4) out4[i] = make_float4(0.f, 0.f, 0.f, 0.f);
}

__device__ __forceinline__ void load_chunk(const float* __restrict__ attrs,
                                           const void* __restrict__ src_idx,
                                           bool is64, long long E, long long group,
                                           int kg, int src[4],
                                           float4& v0, float4& v1,
                                           float4& v2, float4& v3) {
    size_t e0 = (size_t)group * 4;
    if (is64) {
        const longlong2* p = (const longlong2*)src_idx + 2 * group;
        longlong2 a = __ldcs(p);
        longlong2 b = __ldcs(p + 1);
        src[0] = (int)a.x; src[1] = (int)a.y;
        src[2] = (int)b.x; src[3] = (int)b.y;
    } else {
        int4 a = __ldcs((const int4*)src_idx + group);
        src[0] = a.x; src[1] = a.y; src[2] = a.z; src[3] = a.w;
    }
    v0 = __ldcs((const float4*)(attrs + (size_t)(kg + 0) * (size_t)E + e0));
    v1 = __ldcs((const float4*)(attrs + (size_t)(kg + 1) * (size_t)E + e0));
    v2 = __ldcs((const float4*)(attrs + (size_t)(kg + 2) * (size_t)E + e0));
    v3 = __ldcs((const float4*)(attrs + (size_t)(kg + 3) * (size_t)E + e0));
}

__device__ __forceinline__ void red_chunk(float* __restrict__ out, int kg,
                                          const int src[4],
                                          const float4& v0, const float4& v1,
                                          const float4& v2, const float4& v3) {
    const float* c0 = (const float*)&v0;
    const float* c1 = (const float*)&v1;
    const float* c2 = (const float*)&v2;
    const float* c3 = (const float*)&v3;
#pragma unroll
    for (int j = 0; j < 4; j++) {
        float* dst = out + (size_t)src[j] * F + kg;
        asm volatile(
            "red.global.add.v4.f32 [%0], {%1, %2, %3, %4};"
            :: "l"(dst), "f"(c0[j]), "f"(c1[j]), "f"(c2[j]), "f"(c3[j])
            : "memory");
    }
}

__global__ void __launch_bounds__(TPB)
scatter_rt2_kernel(const float* __restrict__ attrs,
                   const void* __restrict__ src_idx,
                   float* __restrict__ out,
                   long long E, long long G2) {
    bool is64 = (g_idx_is64 != 0);

    long long gtid = (long long)blockIdx.x * TPB + threadIdx.x;
    long long ga = gtid >> 2;           // first 4-edge group
    int kg = ((int)gtid & 3) * 4;       // this lane's feature quarter
    if (ga >= G2) return;
    long long gb = ga + G2;             // second 4-edge group

    // Front-batch all 10 loads (2 idx + 8 float4) for MLP.
    int srcA[4], srcB[4];
    float4 a0, a1, a2, a3, b0, b1, b2, b3;
    load_chunk(attrs, src_idx, is64, E, ga, kg, srcA, a0, a1, a2, a3);
    load_chunk(attrs, src_idx, is64, E, gb, kg, srcB, b0, b1, b2, b3);

    red_chunk(out, kg, srcA, a0, a1, a2, a3);
    red_chunk(out, kg, srcB, b0, b1, b2, b3);
}

// Scalar tail for leftover edges (E % 8 != 0; not hit for E=4M).
__global__ void scatter_tail_kernel(const float* __restrict__ attrs,
                                    const void* __restrict__ src_idx,
                                    float* __restrict__ out,
                                    long long E, long long e_begin) {
    bool is64 = (g_idx_is64 != 0);
    long long e = e_begin + (long long)blockIdx.x * blockDim.x + threadIdx.x;
    if (e >= E) return;
    int src = is64 ? (int)((const long long*)src_idx)[e]
                   : ((const int*)src_idx)[e];
    float v[F];
#pragma unroll
    for (int k = 0; k < F; k++) v[k] = attrs[(size_t)k * (size_t)E + e];
    float* dst = out + (size_t)src * F;
#pragma unroll
    for (int kg = 0; kg < F; kg += 4) {
        asm volatile(
            "red.global.add.v4.f32 [%0], {%1, %2, %3, %4};"
            :: "l"(dst + kg), "f"(v[kg]), "f"(v[kg + 1]), "f"(v[kg + 2]), "f"(v[kg + 3])
            : "memory");
    }
}

extern "C" void kernel_launch(void* const* d_in, const int* in_sizes, int n_in,
                              void* d_out, int out_size) {
    const float* attrs = (const float*)d_in[0];
    const void* attr_idx = d_in[1];        // (2, E), row 0 = src
    float* out = (float*)d_out;

    long long E = in_sizes[0] / F;

    int n4 = out_size / 4;
    zero_out_kernel<<<(n4 + 255) / 256, 256>>>((float4*)out, n4,
                                               (const int*)attr_idx, E);

    long long G = E / 4;                   // full 4-edge groups
    long long G2 = G / 2;                  // chunk pairs
    if (G2 > 0) {
        long long n_threads = G2 * 4;
        int blocks = (int)((n_threads + TPB - 1) / TPB);
        scatter_rt2_kernel<<<blocks, TPB>>>(attrs, attr_idx, out, E, G2);
    }

    long long rem_begin = G2 * 8;          // edges covered by paired chunks
    long long rem = E - rem_begin;
    if (rem > 0) {
        int blocks = (int)((rem + 255) / 256);
        scatter_tail_kernel<<<blocks, 256>>>(attrs, attr_idx, out, E, rem_begin);
    }
}